// round 4
// baseline (speedup 1.0000x reference)
#include <cuda_runtime.h>
#include <cuda_bf16.h>
#include <cstdint>
#include <math.h>

// Problem constants (fixed by the dataset; runtime values cross-checked in kernel_launch)
#define BATCH 128
#define HID   1024
#define H2C   512
#define VOCAB 32000
#define TMAXX 64

// ---------------- device scratch (static allocation only) ----------------
// state[parity][dir][B*H2]  — ping-pong across GRU steps
__device__ float         g_state[2][2][BATCH * H2C];
__device__ __nv_bfloat16 g_hcat[(size_t)TMAXX * BATCH * HID];      // [t*B+b][1024] bf16
__device__ __nv_bfloat16 g_wout[(size_t)VOCAB * HID];              // W_out in bf16

// ---------------- fp32 -> bf16 conversion ----------------
__global__ void f32_to_bf16_kernel(const float4* __restrict__ in,
                                   __nv_bfloat162* __restrict__ out, int n4) {
    int i = blockIdx.x * blockDim.x + threadIdx.x;
    if (i < n4) {
        float4 v = in[i];
        out[2 * i + 0] = __floats2bfloat162_rn(v.x, v.y);
        out[2 * i + 1] = __floats2bfloat162_rn(v.z, v.w);
    }
}

// ---------------- small fp32 GEMM (squeeze):  C = relu(A) @ B^T + bias ----------------
__global__ __launch_bounds__(256) void squeeze_kernel(
    const float* __restrict__ A, const float* __restrict__ Bm,
    const float* __restrict__ bias, float* __restrict__ C0, float* __restrict__ C1,
    int K, int N) {
    __shared__ float As[16][68];
    __shared__ float Bs[16][68];

    const int tid = threadIdx.x;
    const int tx = tid & 15, ty = tid >> 4;
    const int m0 = blockIdx.y * 64, n0 = blockIdx.x * 64;
    const int lrow = tid >> 2;
    const int lk   = (tid & 3) * 4;

    float acc[4][4] = {};

    for (int k0 = 0; k0 < K; k0 += 16) {
        float4 av = *(const float4*)(A + (size_t)(m0 + lrow) * K + k0 + lk);
        av.x = fmaxf(av.x, 0.f); av.y = fmaxf(av.y, 0.f);
        av.z = fmaxf(av.z, 0.f); av.w = fmaxf(av.w, 0.f);
        float4 bv = *(const float4*)(Bm + (size_t)(n0 + lrow) * K + k0 + lk);
        As[lk + 0][lrow] = av.x; As[lk + 1][lrow] = av.y;
        As[lk + 2][lrow] = av.z; As[lk + 3][lrow] = av.w;
        Bs[lk + 0][lrow] = bv.x; Bs[lk + 1][lrow] = bv.y;
        Bs[lk + 2][lrow] = bv.z; Bs[lk + 3][lrow] = bv.w;
        __syncthreads();

#pragma unroll
        for (int k = 0; k < 16; k++) {
            float4 a4 = *(const float4*)&As[k][ty * 4];
            float4 b4 = *(const float4*)&Bs[k][tx * 4];
            float a[4] = {a4.x, a4.y, a4.z, a4.w};
            float b[4] = {b4.x, b4.y, b4.z, b4.w};
#pragma unroll
            for (int i = 0; i < 4; i++)
#pragma unroll
                for (int j = 0; j < 4; j++)
                    acc[i][j] += a[i] * b[j];
        }
        __syncthreads();
    }

#pragma unroll
    for (int i = 0; i < 4; i++)
#pragma unroll
        for (int j = 0; j < 4; j++) {
            int m = m0 + ty * 4 + i;
            int n = n0 + tx * 4 + j;
            float v = acc[i][j] + bias[n];
            C0[(size_t)m * N + n] = v;
            C1[(size_t)m * N + n] = v;
        }
}

// ---------------- fused GRU step: gate GEMM + nonlinearity + state update ----------------
// Grid: (H2C/16 = 32 j-slabs, BATCH/64 = 2 batch tiles, 2 dirs). 256 threads.
// CTA computes gh for 64 batch rows x 16 j-cols x 3 gates (48 W rows, K=512),
// then applies gates, writes state[(t+1)&1][dir] and hcat (bf16).
__global__ __launch_bounds__(256) void gru_step_kernel(
    const float* __restrict__ W_hh_f, const float* __restrict__ W_hh_r,
    const float* __restrict__ b_ih_f, const float* __restrict__ b_ih_r,
    const float* __restrict__ b_hh_f, const float* __restrict__ b_hh_r,
    int t, int T) {
    __shared__ float As[32][68];   // [k][batch row]
    __shared__ float Bs[32][52];   // [k][48 gate rows: r0-15, z0-15, n0-15]

    const int dir = blockIdx.z;
    const int b0  = blockIdx.y * 64;
    const int j0  = blockIdx.x * 16;
    const int tid = threadIdx.x;
    const int ty = tid >> 4, tx = tid & 15;   // ty: 4-row group, tx: jl

    const float* __restrict__ W   = dir ? W_hh_r : W_hh_f;
    const float* __restrict__ bih = dir ? b_ih_r : b_ih_f;
    const float* __restrict__ bhh = dir ? b_hh_r : b_hh_f;
    const float* __restrict__ hin  = g_state[t & 1][dir];
    float* __restrict__       hout = g_state[(t + 1) & 1][dir];

    float accR[4] = {}, accZ[4] = {}, accN[4] = {};

    for (int k0 = 0; k0 < H2C; k0 += 32) {
        // fill B: 48 rows x 8 float4
        for (int task = tid; task < 48 * 8; task += 256) {
            int rr = task >> 3;              // 0..47
            int kq = (task & 7) * 4;
            int g  = rr >> 4, jl = rr & 15;
            float4 v = *(const float4*)(W + (size_t)(g * H2C + j0 + jl) * H2C + k0 + kq);
            Bs[kq + 0][rr] = v.x; Bs[kq + 1][rr] = v.y;
            Bs[kq + 2][rr] = v.z; Bs[kq + 3][rr] = v.w;
        }
        // fill A: 64 rows x 8 float4
        for (int task = tid; task < 64 * 8; task += 256) {
            int r  = task >> 3;
            int kq = (task & 7) * 4;
            float4 v = *(const float4*)(hin + (size_t)(b0 + r) * H2C + k0 + kq);
            As[kq + 0][r] = v.x; As[kq + 1][r] = v.y;
            As[kq + 2][r] = v.z; As[kq + 3][r] = v.w;
        }
        __syncthreads();

#pragma unroll
        for (int k = 0; k < 32; k++) {
            float4 a = *(const float4*)&As[k][ty * 4];
            float bR = Bs[k][tx];
            float bZ = Bs[k][16 + tx];
            float bN = Bs[k][32 + tx];
            accR[0] += a.x * bR; accR[1] += a.y * bR; accR[2] += a.z * bR; accR[3] += a.w * bR;
            accZ[0] += a.x * bZ; accZ[1] += a.y * bZ; accZ[2] += a.z * bZ; accZ[3] += a.w * bZ;
            accN[0] += a.x * bN; accN[1] += a.y * bN; accN[2] += a.z * bN; accN[3] += a.w * bN;
        }
        __syncthreads();
    }

    const int j = j0 + tx;
    const float bihR = bih[j], bihZ = bih[H2C + j], bihN = bih[2 * H2C + j];
    const float bhhR = bhh[j], bhhZ = bhh[H2C + j], bhhN = bhh[2 * H2C + j];
    const int tt = dir ? (T - 1 - t) : t;

#pragma unroll
    for (int i = 0; i < 4; i++) {
        const int b = b0 + ty * 4 + i;
        float hold = hin[(size_t)b * H2C + j];
        float r = 1.f / (1.f + __expf(-(bihR + bhhR + accR[i])));
        float z = 1.f / (1.f + __expf(-(bihZ + bhhZ + accZ[i])));
        float n = tanhf(bihN + r * (accN[i] + bhhN));
        float hn = (1.f - z) * n + z * hold;
        hout[(size_t)b * H2C + j] = hn;
        g_hcat[((size_t)tt * BATCH + b) * HID + dir * H2C + j] = __float2bfloat16(hn);
    }
}

// ---------------- big bf16 GEMM: C[M,N] = A[M,K] @ B[N,K]^T + bias ----------------
// BM=128, BN=256, BK=32, 256 threads = 8 warps (2m x 4n), warp tile 64x64,
// mma.sync m16n8k16 bf16, 4-stage cp.async pipeline in dynamic smem.

__device__ __forceinline__ int sw_off(int row, int k) {
    // row stride 32 bf16 (64B); 16B chunks xor-swizzled by (row>>1)&3
    return row * 32 + ((((k >> 3) ^ ((row >> 1) & 3)) & 3) << 3) + (k & 7);
}

__device__ __forceinline__ void cp_async16(uint32_t smem, const void* g) {
    asm volatile("cp.async.cg.shared.global [%0], [%1], 16;\n" :: "r"(smem), "l"(g));
}
__device__ __forceinline__ void cp_commit() {
    asm volatile("cp.async.commit_group;\n" ::: "memory");
}

__device__ __forceinline__ void ldm4(uint32_t& a, uint32_t& b, uint32_t& c, uint32_t& d,
                                     uint32_t addr) {
    asm volatile("ldmatrix.sync.aligned.m8n8.x4.shared.b16 {%0,%1,%2,%3}, [%4];"
                 : "=r"(a), "=r"(b), "=r"(c), "=r"(d) : "r"(addr));
}

__device__ __forceinline__ void mma_bf16(float* c, const uint32_t* a, const uint32_t* b) {
    asm volatile(
        "mma.sync.aligned.m16n8k16.row.col.f32.bf16.bf16.f32 "
        "{%0,%1,%2,%3}, {%4,%5,%6,%7}, {%8,%9}, {%0,%1,%2,%3};"
        : "+f"(c[0]), "+f"(c[1]), "+f"(c[2]), "+f"(c[3])
        : "r"(a[0]), "r"(a[1]), "r"(a[2]), "r"(a[3]), "r"(b[0]), "r"(b[1]));
}

#define BG_ABYTES 8192     // 128 rows x 32 k x 2B per stage
#define BG_BBYTES 16384    // 256 rows x 32 k x 2B per stage
#define BG_NSTG   4

__global__ __launch_bounds__(256, 1) void gemm_big_bf16(
    const __nv_bfloat16* __restrict__ Ag, const __nv_bfloat16* __restrict__ Bg,
    const float* __restrict__ bias, float* __restrict__ Cg,
    int M, int N, int K) {
    extern __shared__ __align__(128) char dsm[];
    const uint32_t sa = (uint32_t)__cvta_generic_to_shared(dsm);
    const uint32_t saA = sa;                              // 4 stages x 8KB
    const uint32_t saB = sa + BG_NSTG * BG_ABYTES;        // 4 stages x 16KB

    const int tid = threadIdx.x;
    const int warp = tid >> 5, lane = tid & 31;
    const int wm = warp >> 2, wn = warp & 3;
    const int m0 = blockIdx.x * 128, n0 = blockIdx.y * 256;

    // cp.async fill: r0 = tid>>2 (64 rows), c0 = tid&3 (16B chunk)
    const int r0 = tid >> 2, c0 = tid & 3;
    const uint32_t off0 = (uint32_t)sw_off(r0,       c0 * 8) * 2;
    const uint32_t off1 = (uint32_t)sw_off(r0 + 64,  c0 * 8) * 2;
    const uint32_t off2 = (uint32_t)sw_off(r0 + 128, c0 * 8) * 2;
    const uint32_t off3 = (uint32_t)sw_off(r0 + 192, c0 * 8) * 2;

    const __nv_bfloat16* Arow0 = Ag + (size_t)(m0 + r0) * K + c0 * 8;
    const __nv_bfloat16* Arow1 = Ag + (size_t)(m0 + r0 + 64) * K + c0 * 8;
    const __nv_bfloat16* Brow0 = Bg + (size_t)(n0 + r0) * K + c0 * 8;
    const __nv_bfloat16* Brow1 = Bg + (size_t)(n0 + r0 + 64) * K + c0 * 8;
    const __nv_bfloat16* Brow2 = Bg + (size_t)(n0 + r0 + 128) * K + c0 * 8;
    const __nv_bfloat16* Brow3 = Bg + (size_t)(n0 + r0 + 192) * K + c0 * 8;

    float acc[4][8][4] = {};
    const int NK = K / 32;   // 32

    auto load_stage = [&](int kt) {
        const int s = kt & (BG_NSTG - 1);
        const uint32_t ba = saA + (uint32_t)(s * BG_ABYTES);
        const uint32_t bb = saB + (uint32_t)(s * BG_BBYTES);
        cp_async16(ba + off0, Arow0 + kt * 32);
        cp_async16(ba + off1, Arow1 + kt * 32);
        cp_async16(bb + off0, Brow0 + kt * 32);
        cp_async16(bb + off1, Brow1 + kt * 32);
        cp_async16(bb + off2, Brow2 + kt * 32);
        cp_async16(bb + off3, Brow3 + kt * 32);
        cp_commit();
    };

    load_stage(0);
    load_stage(1);
    load_stage(2);

    for (int kt = 0; kt < NK; kt++) {
        if (kt + 3 < NK) {
            load_stage(kt + 3);
            asm volatile("cp.async.wait_group 3;\n" ::: "memory");
        } else if (kt + 2 < NK) {
            asm volatile("cp.async.wait_group 2;\n" ::: "memory");
        } else if (kt + 1 < NK) {
            asm volatile("cp.async.wait_group 1;\n" ::: "memory");
        } else {
            asm volatile("cp.async.wait_group 0;\n" ::: "memory");
        }
        __syncthreads();

        const int s = kt & (BG_NSTG - 1);
        const uint32_t baseA = saA + (uint32_t)(s * BG_ABYTES);
        const uint32_t baseB = saB + (uint32_t)(s * BG_BBYTES);

#pragma unroll
        for (int ks = 0; ks < 32; ks += 16) {
            uint32_t afr[4][4];
#pragma unroll
            for (int mi = 0; mi < 4; mi++) {
                int row = wm * 64 + mi * 16 + (lane & 15);
                int kk = ks + ((lane >> 4) << 3);
                ldm4(afr[mi][0], afr[mi][1], afr[mi][2], afr[mi][3],
                     baseA + (uint32_t)sw_off(row, kk) * 2);
            }
            uint32_t bfr[8][2];
#pragma unroll
            for (int ni = 0; ni < 4; ni++) {
                int row = wn * 64 + ni * 16 + ((lane >> 4) << 3) + (lane & 7);
                int kk = ks + (((lane >> 3) & 1) << 3);
                uint32_t q0, q1, q2, q3;
                ldm4(q0, q1, q2, q3, baseB + (uint32_t)sw_off(row, kk) * 2);
                bfr[ni * 2 + 0][0] = q0; bfr[ni * 2 + 0][1] = q1;
                bfr[ni * 2 + 1][0] = q2; bfr[ni * 2 + 1][1] = q3;
            }
#pragma unroll
            for (int mi = 0; mi < 4; mi++)
#pragma unroll
                for (int nf = 0; nf < 8; nf++)
                    mma_bf16(acc[mi][nf], afr[mi], bfr[nf]);
        }
        __syncthreads();
    }

    // epilogue: add bias, fp32 store
#pragma unroll
    for (int mi = 0; mi < 4; mi++) {
#pragma unroll
        for (int nf = 0; nf < 8; nf++) {
            int row = m0 + wm * 64 + mi * 16 + (lane >> 2);
            int col = n0 + wn * 64 + nf * 8 + (lane & 3) * 2;
            float b0 = bias[col], b1 = bias[col + 1];
            float2 v0 = make_float2(acc[mi][nf][0] + b0, acc[mi][nf][1] + b1);
            float2 v1 = make_float2(acc[mi][nf][2] + b0, acc[mi][nf][3] + b1);
            *(float2*)&Cg[(size_t)row * N + col] = v0;
            *(float2*)&Cg[(size_t)(row + 8) * N + col] = v1;
        }
    }
}

// ---------------- in-place log_softmax over rows of length V ----------------
__device__ float block_reduce(float v, float* red, bool is_max) {
    __syncthreads();
#pragma unroll
    for (int o = 16; o; o >>= 1) {
        float w = __shfl_xor_sync(0xffffffff, v, o);
        v = is_max ? fmaxf(v, w) : (v + w);
    }
    if ((threadIdx.x & 31) == 0) red[threadIdx.x >> 5] = v;
    __syncthreads();
    if (threadIdx.x < 32) {
        float w = (threadIdx.x < (blockDim.x >> 5)) ? red[threadIdx.x]
                                                    : (is_max ? -INFINITY : 0.f);
#pragma unroll
        for (int o = 16; o; o >>= 1) {
            float u = __shfl_xor_sync(0xffffffff, w, o);
            w = is_max ? fmaxf(w, u) : (w + u);
        }
        if (threadIdx.x == 0) red[0] = w;
    }
    __syncthreads();
    return red[0];
}

__global__ void logsoftmax_kernel(float* __restrict__ out, int V) {
    extern __shared__ float row[];
    __shared__ float red[32];
    float* x = out + (size_t)blockIdx.x * V;
    const int tid = threadIdx.x;

    float mx = -INFINITY;
    for (int i = tid * 4; i < V; i += blockDim.x * 4) {
        float4 v = *(const float4*)(x + i);
        *(float4*)(row + i) = v;
        mx = fmaxf(mx, fmaxf(fmaxf(v.x, v.y), fmaxf(v.z, v.w)));
    }
    mx = block_reduce(mx, red, true);

    float s = 0.f;
    for (int i = tid * 4; i < V; i += blockDim.x * 4) {
        float4 v = *(const float4*)(row + i);
        s += expf(v.x - mx) + expf(v.y - mx) + expf(v.z - mx) + expf(v.w - mx);
    }
    s = block_reduce(s, red, false);
    const float lse = mx + logf(s);

    for (int i = tid * 4; i < V; i += blockDim.x * 4) {
        float4 v = *(const float4*)(row + i);
        v.x -= lse; v.y -= lse; v.z -= lse; v.w -= lse;
        *(float4*)(x + i) = v;
    }
}

// ---------------- launcher ----------------
extern "C" void kernel_launch(void* const* d_in, const int* in_sizes, int n_in,
                              void* d_out, int out_size) {
    const float* hidden = (const float*)d_in[0];
    const float* W_sq   = (const float*)d_in[1];
    const float* b_sq   = (const float*)d_in[2];
    const float* W_hh_f = (const float*)d_in[3];
    const float* b_ih_f = (const float*)d_in[4];
    const float* b_hh_f = (const float*)d_in[5];
    const float* W_hh_r = (const float*)d_in[6];
    const float* b_ih_r = (const float*)d_in[7];
    const float* b_hh_r = (const float*)d_in[8];
    const float* W_out  = (const float*)d_in[9];
    const float* b_out  = (const float*)d_in[10];
    float* out = (float*)d_out;

    const int h2 = in_sizes[2];              // 512
    const int Hh = 2 * h2;                   // 1024
    const int Bb = in_sizes[0] / Hh;         // 128
    const int V  = in_sizes[10];             // 32000
    const int T  = out_size / (Bb * V);      // 32
    if (T > TMAXX) return;

    float* state_base;
    __nv_bfloat16 *hcat, *wout;
    cudaGetSymbolAddress((void**)&state_base, g_state);
    cudaGetSymbolAddress((void**)&hcat, g_hcat);
    cudaGetSymbolAddress((void**)&wout, g_wout);
    float* st00 = state_base;                      // parity 0, dir 0
    float* st01 = state_base + BATCH * H2C;        // parity 0, dir 1

    // 1. W_out -> bf16
    {
        int n4 = V * Hh / 4;
        f32_to_bf16_kernel<<<(n4 + 255) / 256, 256>>>(
            (const float4*)W_out, (__nv_bfloat162*)wout, n4);
    }

    // 2. squeeze: enc = relu(hidden) @ W_sq^T + b_sq   -> parity-0 state, both dirs
    squeeze_kernel<<<dim3(h2 / 64, Bb / 64), 256>>>(
        hidden, W_sq, b_sq, st00, st01, Hh, h2);

    // 3. GRU recurrence: one fused launch per step, both dirs
    for (int t = 0; t < T; t++) {
        gru_step_kernel<<<dim3(h2 / 16, Bb / 64, 2), 256>>>(
            W_hh_f, W_hh_r, b_ih_f, b_ih_r, b_hh_f, b_hh_r, t, T);
    }

    // 4. logits = hcat @ W_out^T + b_out  (bf16 tensor cores, fp32 accum)
    {
        const int M = T * Bb;   // 4096
        const int smem = BG_NSTG * (BG_ABYTES + BG_BBYTES);   // 98304
        cudaFuncSetAttribute(gemm_big_bf16,
                             cudaFuncAttributeMaxDynamicSharedMemorySize, smem);
        gemm_big_bf16<<<dim3(M / 128, V / 256), 256, smem>>>(
            hcat, wout, b_out, out, M, V, Hh);
    }

    // 5. in-place log_softmax per row
    cudaFuncSetAttribute(logsoftmax_kernel,
                         cudaFuncAttributeMaxDynamicSharedMemorySize,
                         V * (int)sizeof(float));
    logsoftmax_kernel<<<T * Bb, 1024, V * sizeof(float)>>>(out, V);
}

// round 5
// speedup vs baseline: 1.5871x; 1.5871x over previous
#include <cuda_runtime.h>
#include <cuda_bf16.h>
#include <cstdint>
#include <math.h>

// Problem constants (fixed by the dataset; runtime values cross-checked in kernel_launch)
#define BATCH 128
#define HID   1024
#define H2C   512
#define VOCAB 32000
#define TMAXX 64

// ---------------- device scratch (static allocation only) ----------------
__device__ float         g_state_f[2][2][BATCH * H2C];   // fp32 master state [parity][dir]
__device__ __nv_bfloat16 g_state_h[2][2][BATCH * H2C];   // bf16 copy for MMA A operand
__device__ __nv_bfloat16 g_whh16[2][3 * H2C * H2C];      // W_hh in bf16 per dir
__device__ __nv_bfloat16 g_hcat[(size_t)TMAXX * BATCH * HID];  // [t*B+b][1024] bf16
__device__ __nv_bfloat16 g_wout[(size_t)VOCAB * HID];          // W_out in bf16

// ---------------- fp32 -> bf16 conversion ----------------
__global__ void f32_to_bf16_kernel(const float4* __restrict__ in,
                                   __nv_bfloat162* __restrict__ out, int n4) {
    int i = blockIdx.x * blockDim.x + threadIdx.x;
    if (i < n4) {
        float4 v = in[i];
        out[2 * i + 0] = __floats2bfloat162_rn(v.x, v.y);
        out[2 * i + 1] = __floats2bfloat162_rn(v.z, v.w);
    }
}

// ---------------- small fp32 GEMM (squeeze):  C = relu(A) @ B^T + bias ----------------
// Writes fp32 state (both dirs) and bf16 state copies (both dirs), parity 0.
__global__ __launch_bounds__(256) void squeeze_kernel(
    const float* __restrict__ A, const float* __restrict__ Bm,
    const float* __restrict__ bias,
    float* __restrict__ F0, float* __restrict__ F1,
    __nv_bfloat16* __restrict__ Hh0, __nv_bfloat16* __restrict__ Hh1,
    int K, int N) {
    __shared__ float As[16][68];
    __shared__ float Bs[16][68];

    const int tid = threadIdx.x;
    const int tx = tid & 15, ty = tid >> 4;
    const int m0 = blockIdx.y * 64, n0 = blockIdx.x * 64;
    const int lrow = tid >> 2;
    const int lk   = (tid & 3) * 4;

    float acc[4][4] = {};

    for (int k0 = 0; k0 < K; k0 += 16) {
        float4 av = *(const float4*)(A + (size_t)(m0 + lrow) * K + k0 + lk);
        av.x = fmaxf(av.x, 0.f); av.y = fmaxf(av.y, 0.f);
        av.z = fmaxf(av.z, 0.f); av.w = fmaxf(av.w, 0.f);
        float4 bv = *(const float4*)(Bm + (size_t)(n0 + lrow) * K + k0 + lk);
        As[lk + 0][lrow] = av.x; As[lk + 1][lrow] = av.y;
        As[lk + 2][lrow] = av.z; As[lk + 3][lrow] = av.w;
        Bs[lk + 0][lrow] = bv.x; Bs[lk + 1][lrow] = bv.y;
        Bs[lk + 2][lrow] = bv.z; Bs[lk + 3][lrow] = bv.w;
        __syncthreads();

#pragma unroll
        for (int k = 0; k < 16; k++) {
            float4 a4 = *(const float4*)&As[k][ty * 4];
            float4 b4 = *(const float4*)&Bs[k][tx * 4];
            float a[4] = {a4.x, a4.y, a4.z, a4.w};
            float b[4] = {b4.x, b4.y, b4.z, b4.w};
#pragma unroll
            for (int i = 0; i < 4; i++)
#pragma unroll
                for (int j = 0; j < 4; j++)
                    acc[i][j] += a[i] * b[j];
        }
        __syncthreads();
    }

#pragma unroll
    for (int i = 0; i < 4; i++)
#pragma unroll
        for (int j = 0; j < 4; j++) {
            int m = m0 + ty * 4 + i;
            int n = n0 + tx * 4 + j;
            float v = acc[i][j] + bias[n];
            __nv_bfloat16 vh = __float2bfloat16(v);
            F0[(size_t)m * N + n] = v;
            F1[(size_t)m * N + n] = v;
            Hh0[(size_t)m * N + n] = vh;
            Hh1[(size_t)m * N + n] = vh;
        }
}

// ---------------- shared mma helpers ----------------
__device__ __forceinline__ void cp_async16(uint32_t smem, const void* g) {
    asm volatile("cp.async.cg.shared.global [%0], [%1], 16;\n" :: "r"(smem), "l"(g));
}
__device__ __forceinline__ void cp_commit() {
    asm volatile("cp.async.commit_group;\n" ::: "memory");
}
__device__ __forceinline__ void ldm4(uint32_t& a, uint32_t& b, uint32_t& c, uint32_t& d,
                                     uint32_t addr) {
    asm volatile("ldmatrix.sync.aligned.m8n8.x4.shared.b16 {%0,%1,%2,%3}, [%4];"
                 : "=r"(a), "=r"(b), "=r"(c), "=r"(d) : "r"(addr));
}
__device__ __forceinline__ void ldm2(uint32_t& a, uint32_t& b, uint32_t addr) {
    asm volatile("ldmatrix.sync.aligned.m8n8.x2.shared.b16 {%0,%1}, [%2];"
                 : "=r"(a), "=r"(b) : "r"(addr));
}
__device__ __forceinline__ void mma_bf16(float* c, const uint32_t* a, const uint32_t* b) {
    asm volatile(
        "mma.sync.aligned.m16n8k16.row.col.f32.bf16.bf16.f32 "
        "{%0,%1,%2,%3}, {%4,%5,%6,%7}, {%8,%9}, {%0,%1,%2,%3};"
        : "+f"(c[0]), "+f"(c[1]), "+f"(c[2]), "+f"(c[3])
        : "r"(a[0]), "r"(a[1]), "r"(a[2]), "r"(a[3]), "r"(b[0]), "r"(b[1]));
}

// ---------------- GRU step on tensor cores ----------------
// Grid: (H2C/32 = 16 j-slabs, BATCH/64 = 2 m-halves, 2 dirs) = 64 CTAs, 256 threads.
// A = h_bf16 [64 x 512] (one-shot into smem), B = W slab [3 gates x 32 j][512] bf16.
// 8 warps = 2(m: 32 rows) x 4(n: 8 j). Warp: 2 m-tiles x 1 n-tile x 3 gates.
// Epilogue applies gates, writes fp32 state, bf16 state, hcat.

// smem element offset, row stride 512 bf16 (1024B), 16B-chunk swizzle by row&7
__device__ __forceinline__ int toff(int row, int k) {
    return row * 512 + (((k >> 3) ^ (row & 7)) << 3) + (k & 7);
}

#define GRU_SMA (64 * 512 * 2)    // 64KB A
#define GRU_SMB (96 * 512 * 2)    // 96KB B

__global__ __launch_bounds__(256, 1) void gru_mma_kernel(
    const float* __restrict__ b_ih_f, const float* __restrict__ b_ih_r,
    const float* __restrict__ b_hh_f, const float* __restrict__ b_hh_r,
    int t, int T) {
    extern __shared__ __align__(128) char dsm[];
    const uint32_t saA = (uint32_t)__cvta_generic_to_shared(dsm);
    const uint32_t saB = saA + GRU_SMA;

    const int dir = blockIdx.z;
    const int bm0 = blockIdx.y * 64;
    const int j0  = blockIdx.x * 32;
    const int tid = threadIdx.x;
    const int warp = tid >> 5, lane = tid & 31;
    const int wm = warp >> 2, wn = warp & 3;

    const int pin = t & 1, pout = (t + 1) & 1;
    const __nv_bfloat16* __restrict__ Ah = g_state_h[pin][dir];
    const float* __restrict__ Fin  = g_state_f[pin][dir];
    float* __restrict__ Fout       = g_state_f[pout][dir];
    __nv_bfloat16* __restrict__ Hout = g_state_h[pout][dir];
    const __nv_bfloat16* __restrict__ W16 = g_whh16[dir];
    const float* __restrict__ bih = dir ? b_ih_r : b_ih_f;
    const float* __restrict__ bhh = dir ? b_hh_r : b_hh_f;

    // one-shot load: A 64x512 (4096 chunks), B 96x512 (6144 chunks)
    for (int c = tid; c < 4096; c += 256) {
        int row = c >> 6, ch = c & 63;
        cp_async16(saA + (uint32_t)(row * 512 + ((ch ^ (row & 7)) << 3)) * 2,
                   Ah + (size_t)(bm0 + row) * 512 + ch * 8);
    }
    for (int c = tid; c < 6144; c += 256) {
        int row = c >> 6, ch = c & 63;
        int gate = row >> 5, jl = row & 31;
        cp_async16(saB + (uint32_t)(row * 512 + ((ch ^ (row & 7)) << 3)) * 2,
                   W16 + (size_t)(gate * H2C + j0 + jl) * 512 + ch * 8);
    }
    cp_commit();
    asm volatile("cp.async.wait_group 0;\n" ::: "memory");
    __syncthreads();

    float acc[2][3][4] = {};   // [m-tile][gate][frag]

#pragma unroll 4
    for (int ks = 0; ks < 32; ks++) {
        const int kk0 = ks * 16;
        uint32_t afr[2][4];
#pragma unroll
        for (int mt = 0; mt < 2; mt++) {
            int row = wm * 32 + mt * 16 + (lane & 15);
            int kk = kk0 + ((lane >> 4) << 3);
            ldm4(afr[mt][0], afr[mt][1], afr[mt][2], afr[mt][3],
                 saA + (uint32_t)toff(row, kk) * 2);
        }
        uint32_t bfr[3][2];
#pragma unroll
        for (int g = 0; g < 3; g++) {
            int row = g * 32 + wn * 8 + (lane & 7);
            int kk = kk0 + (((lane >> 3) & 1) << 3);
            ldm2(bfr[g][0], bfr[g][1], saB + (uint32_t)toff(row, kk) * 2);
        }
#pragma unroll
        for (int mt = 0; mt < 2; mt++)
#pragma unroll
            for (int g = 0; g < 3; g++)
                mma_bf16(acc[mt][g], afr[mt], bfr[g]);
    }

    // epilogue: gates + state update + hcat write
    const int tt = dir ? (T - 1 - t) : t;
    const int jbase = j0 + wn * 8 + (lane & 3) * 2;

#pragma unroll
    for (int cc = 0; cc < 2; cc++) {
        const int j = jbase + cc;
        const float biR = bih[j]          + bhh[j];
        const float biZ = bih[H2C + j]    + bhh[H2C + j];
        const float biN = bih[2 * H2C + j];
        const float bhN = bhh[2 * H2C + j];
#pragma unroll
        for (int mt = 0; mt < 2; mt++) {
            const int bb = bm0 + wm * 32 + mt * 16 + (lane >> 2);
#pragma unroll
            for (int rh = 0; rh < 2; rh++) {
                const int b = bb + rh * 8;
                const int idx = rh * 2 + cc;
                float r = 1.f / (1.f + __expf(-(biR + acc[mt][0][idx])));
                float z = 1.f / (1.f + __expf(-(biZ + acc[mt][1][idx])));
                float n = tanhf(biN + r * (acc[mt][2][idx] + bhN));
                float hold = Fin[(size_t)b * H2C + j];
                float hn = (1.f - z) * n + z * hold;
                Fout[(size_t)b * H2C + j] = hn;
                __nv_bfloat16 hb = __float2bfloat16(hn);
                Hout[(size_t)b * H2C + j] = hb;
                g_hcat[((size_t)tt * BATCH + b) * HID + dir * H2C + j] = hb;
            }
        }
    }
}

// ---------------- big bf16 GEMM: C[M,N] = A[M,K] @ B[N,K]^T + bias ----------------
// BM=128, BN=256, BK=32, 256 threads = 8 warps (2m x 4n), warp tile 64x64,
// mma.sync m16n8k16 bf16, 4-stage cp.async pipeline in dynamic smem.

__device__ __forceinline__ int sw_off(int row, int k) {
    // row stride 32 bf16 (64B); 16B chunks xor-swizzled by (row>>1)&3
    return row * 32 + ((((k >> 3) ^ ((row >> 1) & 3)) & 3) << 3) + (k & 7);
}

#define BG_ABYTES 8192     // 128 rows x 32 k x 2B per stage
#define BG_BBYTES 16384    // 256 rows x 32 k x 2B per stage
#define BG_NSTG   4

__global__ __launch_bounds__(256, 1) void gemm_big_bf16(
    const __nv_bfloat16* __restrict__ Ag, const __nv_bfloat16* __restrict__ Bg,
    const float* __restrict__ bias, float* __restrict__ Cg,
    int M, int N, int K) {
    extern __shared__ __align__(128) char dsm[];
    const uint32_t sa = (uint32_t)__cvta_generic_to_shared(dsm);
    const uint32_t saA = sa;                              // 4 stages x 8KB
    const uint32_t saB = sa + BG_NSTG * BG_ABYTES;        // 4 stages x 16KB

    const int tid = threadIdx.x;
    const int warp = tid >> 5, lane = tid & 31;
    const int wm = warp >> 2, wn = warp & 3;
    const int m0 = blockIdx.x * 128, n0 = blockIdx.y * 256;

    const int r0 = tid >> 2, c0 = tid & 3;
    const uint32_t off0 = (uint32_t)sw_off(r0,       c0 * 8) * 2;
    const uint32_t off1 = (uint32_t)sw_off(r0 + 64,  c0 * 8) * 2;
    const uint32_t off2 = (uint32_t)sw_off(r0 + 128, c0 * 8) * 2;
    const uint32_t off3 = (uint32_t)sw_off(r0 + 192, c0 * 8) * 2;

    const __nv_bfloat16* Arow0 = Ag + (size_t)(m0 + r0) * K + c0 * 8;
    const __nv_bfloat16* Arow1 = Ag + (size_t)(m0 + r0 + 64) * K + c0 * 8;
    const __nv_bfloat16* Brow0 = Bg + (size_t)(n0 + r0) * K + c0 * 8;
    const __nv_bfloat16* Brow1 = Bg + (size_t)(n0 + r0 + 64) * K + c0 * 8;
    const __nv_bfloat16* Brow2 = Bg + (size_t)(n0 + r0 + 128) * K + c0 * 8;
    const __nv_bfloat16* Brow3 = Bg + (size_t)(n0 + r0 + 192) * K + c0 * 8;

    float acc[4][8][4] = {};
    const int NK = K / 32;   // 32

    auto load_stage = [&](int kt) {
        const int s = kt & (BG_NSTG - 1);
        const uint32_t ba = saA + (uint32_t)(s * BG_ABYTES);
        const uint32_t bb = saB + (uint32_t)(s * BG_BBYTES);
        cp_async16(ba + off0, Arow0 + kt * 32);
        cp_async16(ba + off1, Arow1 + kt * 32);
        cp_async16(bb + off0, Brow0 + kt * 32);
        cp_async16(bb + off1, Brow1 + kt * 32);
        cp_async16(bb + off2, Brow2 + kt * 32);
        cp_async16(bb + off3, Brow3 + kt * 32);
        cp_commit();
    };

    load_stage(0);
    load_stage(1);
    load_stage(2);

    for (int kt = 0; kt < NK; kt++) {
        if (kt + 3 < NK) {
            load_stage(kt + 3);
            asm volatile("cp.async.wait_group 3;\n" ::: "memory");
        } else if (kt + 2 < NK) {
            asm volatile("cp.async.wait_group 2;\n" ::: "memory");
        } else if (kt + 1 < NK) {
            asm volatile("cp.async.wait_group 1;\n" ::: "memory");
        } else {
            asm volatile("cp.async.wait_group 0;\n" ::: "memory");
        }
        __syncthreads();

        const int s = kt & (BG_NSTG - 1);
        const uint32_t baseA = saA + (uint32_t)(s * BG_ABYTES);
        const uint32_t baseB = saB + (uint32_t)(s * BG_BBYTES);

#pragma unroll
        for (int ks = 0; ks < 32; ks += 16) {
            uint32_t afr[4][4];
#pragma unroll
            for (int mi = 0; mi < 4; mi++) {
                int row = wm * 64 + mi * 16 + (lane & 15);
                int kk = ks + ((lane >> 4) << 3);
                ldm4(afr[mi][0], afr[mi][1], afr[mi][2], afr[mi][3],
                     baseA + (uint32_t)sw_off(row, kk) * 2);
            }
            uint32_t bfr[8][2];
#pragma unroll
            for (int ni = 0; ni < 4; ni++) {
                int row = wn * 64 + ni * 16 + ((lane >> 4) << 3) + (lane & 7);
                int kk = ks + (((lane >> 3) & 1) << 3);
                uint32_t q0, q1, q2, q3;
                ldm4(q0, q1, q2, q3, baseB + (uint32_t)sw_off(row, kk) * 2);
                bfr[ni * 2 + 0][0] = q0; bfr[ni * 2 + 0][1] = q1;
                bfr[ni * 2 + 1][0] = q2; bfr[ni * 2 + 1][1] = q3;
            }
#pragma unroll
            for (int mi = 0; mi < 4; mi++)
#pragma unroll
                for (int nf = 0; nf < 8; nf++)
                    mma_bf16(acc[mi][nf], afr[mi], bfr[nf]);
        }
        __syncthreads();
    }

#pragma unroll
    for (int mi = 0; mi < 4; mi++) {
#pragma unroll
        for (int nf = 0; nf < 8; nf++) {
            int row = m0 + wm * 64 + mi * 16 + (lane >> 2);
            int col = n0 + wn * 64 + nf * 8 + (lane & 3) * 2;
            float b0 = bias[col], b1 = bias[col + 1];
            float2 v0 = make_float2(acc[mi][nf][0] + b0, acc[mi][nf][1] + b1);
            float2 v1 = make_float2(acc[mi][nf][2] + b0, acc[mi][nf][3] + b1);
            *(float2*)&Cg[(size_t)row * N + col] = v0;
            *(float2*)&Cg[(size_t)(row + 8) * N + col] = v1;
        }
    }
}

// ---------------- in-place log_softmax over rows of length V ----------------
__device__ float block_reduce(float v, float* red, bool is_max) {
    __syncthreads();
#pragma unroll
    for (int o = 16; o; o >>= 1) {
        float w = __shfl_xor_sync(0xffffffff, v, o);
        v = is_max ? fmaxf(v, w) : (v + w);
    }
    if ((threadIdx.x & 31) == 0) red[threadIdx.x >> 5] = v;
    __syncthreads();
    if (threadIdx.x < 32) {
        float w = (threadIdx.x < (blockDim.x >> 5)) ? red[threadIdx.x]
                                                    : (is_max ? -INFINITY : 0.f);
#pragma unroll
        for (int o = 16; o; o >>= 1) {
            float u = __shfl_xor_sync(0xffffffff, w, o);
            w = is_max ? fmaxf(w, u) : (w + u);
        }
        if (threadIdx.x == 0) red[0] = w;
    }
    __syncthreads();
    return red[0];
}

__global__ void logsoftmax_kernel(float* __restrict__ out, int V) {
    extern __shared__ float row[];
    __shared__ float red[32];
    float* x = out + (size_t)blockIdx.x * V;
    const int tid = threadIdx.x;

    float mx = -INFINITY;
    for (int i = tid * 4; i < V; i += blockDim.x * 4) {
        float4 v = *(const float4*)(x + i);
        *(float4*)(row + i) = v;
        mx = fmaxf(mx, fmaxf(fmaxf(v.x, v.y), fmaxf(v.z, v.w)));
    }
    mx = block_reduce(mx, red, true);

    float s = 0.f;
    for (int i = tid * 4; i < V; i += blockDim.x * 4) {
        float4 v = *(const float4*)(row + i);
        s += expf(v.x - mx) + expf(v.y - mx) + expf(v.z - mx) + expf(v.w - mx);
    }
    s = block_reduce(s, red, false);
    const float lse = mx + logf(s);

    for (int i = tid * 4; i < V; i += blockDim.x * 4) {
        float4 v = *(const float4*)(row + i);
        v.x -= lse; v.y -= lse; v.z -= lse; v.w -= lse;
        *(float4*)(x + i) = v;
    }
}

// ---------------- launcher ----------------
extern "C" void kernel_launch(void* const* d_in, const int* in_sizes, int n_in,
                              void* d_out, int out_size) {
    const float* hidden = (const float*)d_in[0];
    const float* W_sq   = (const float*)d_in[1];
    const float* b_sq   = (const float*)d_in[2];
    const float* W_hh_f = (const float*)d_in[3];
    const float* b_ih_f = (const float*)d_in[4];
    const float* b_hh_f = (const float*)d_in[5];
    const float* W_hh_r = (const float*)d_in[6];
    const float* b_ih_r = (const float*)d_in[7];
    const float* b_hh_r = (const float*)d_in[8];
    const float* W_out  = (const float*)d_in[9];
    const float* b_out  = (const float*)d_in[10];
    float* out = (float*)d_out;

    const int h2 = in_sizes[2];              // 512
    const int Hh = 2 * h2;                   // 1024
    const int Bb = in_sizes[0] / Hh;         // 128
    const int V  = in_sizes[10];             // 32000
    const int T  = out_size / (Bb * V);      // 32
    if (T > TMAXX) return;

    float* stf;
    __nv_bfloat16 *sth, *whh16, *hcat, *wout;
    cudaGetSymbolAddress((void**)&stf, g_state_f);
    cudaGetSymbolAddress((void**)&sth, g_state_h);
    cudaGetSymbolAddress((void**)&whh16, g_whh16);
    cudaGetSymbolAddress((void**)&hcat, g_hcat);
    cudaGetSymbolAddress((void**)&wout, g_wout);

    // 1. conversions: W_out, W_hh_fwd, W_hh_rev -> bf16
    {
        int n4 = V * Hh / 4;
        f32_to_bf16_kernel<<<(n4 + 255) / 256, 256>>>(
            (const float4*)W_out, (__nv_bfloat162*)wout, n4);
        int g4 = 3 * h2 * h2 / 4;
        f32_to_bf16_kernel<<<(g4 + 255) / 256, 256>>>(
            (const float4*)W_hh_f, (__nv_bfloat162*)whh16, g4);
        f32_to_bf16_kernel<<<(g4 + 255) / 256, 256>>>(
            (const float4*)W_hh_r, (__nv_bfloat162*)(whh16 + 3 * H2C * H2C), g4);
    }

    // 2. squeeze -> parity-0 state (fp32 + bf16, both dirs)
    squeeze_kernel<<<dim3(h2 / 64, Bb / 64), 256>>>(
        hidden, W_sq, b_sq,
        stf, stf + BATCH * H2C,
        sth, sth + BATCH * H2C, Hh, h2);

    // 3. GRU recurrence: one tensor-core launch per step, both dirs
    {
        const int smem = GRU_SMA + GRU_SMB;   // 160KB
        cudaFuncSetAttribute(gru_mma_kernel,
                             cudaFuncAttributeMaxDynamicSharedMemorySize, smem);
        for (int t = 0; t < T; t++) {
            gru_mma_kernel<<<dim3(h2 / 32, Bb / 64, 2), 256, smem>>>(
                b_ih_f, b_ih_r, b_hh_f, b_hh_r, t, T);
        }
    }

    // 4. logits = hcat @ W_out^T + b_out  (bf16 tensor cores, fp32 accum)
    {
        const int M = T * Bb;   // 4096
        const int smem = BG_NSTG * (BG_ABYTES + BG_BBYTES);   // 98304
        cudaFuncSetAttribute(gemm_big_bf16,
                             cudaFuncAttributeMaxDynamicSharedMemorySize, smem);
        gemm_big_bf16<<<dim3(M / 128, V / 256), 256, smem>>>(
            hcat, wout, b_out, out, M, V, Hh);
    }

    // 5. in-place log_softmax per row
    cudaFuncSetAttribute(logsoftmax_kernel,
                         cudaFuncAttributeMaxDynamicSharedMemorySize,
                         V * (int)sizeof(float));
    logsoftmax_kernel<<<T * Bb, 1024, V * sizeof(float)>>>(out, V);
}

// round 6
// speedup vs baseline: 1.7124x; 1.0789x over previous
#include <cuda_runtime.h>
#include <cuda_bf16.h>
#include <cstdint>
#include <math.h>

// Problem constants (fixed by the dataset; runtime values cross-checked in kernel_launch)
#define BATCH 128
#define HID   1024
#define H2C   512
#define VOCAB 32000
#define TMAXX 64

// ---------------- device scratch (static allocation only) ----------------
__device__ float         g_state_f[2][2][BATCH * H2C];   // fp32 master state [parity][dir]
__device__ __nv_bfloat16 g_state_h[2][2][BATCH * H2C];   // bf16 copy for MMA A operand
__device__ __nv_bfloat16 g_whh16[2][3 * H2C * H2C];      // W_hh in bf16 per dir
__device__ __nv_bfloat16 g_hcat[(size_t)TMAXX * BATCH * HID];  // [t*B+b][1024] bf16
__device__ __nv_bfloat16 g_wout[(size_t)VOCAB * HID];          // W_out in bf16
__device__ __nv_bfloat16 g_enc16[BATCH * HID];                 // relu(hidden) bf16
__device__ __nv_bfloat16 g_wsq16[H2C * HID];                   // W_sq bf16
__device__ unsigned g_bar = 0;                                 // grid barrier counter
__device__ unsigned g_gen = 0;                                 // grid barrier generation

// ---------------- fp32 -> bf16 conversion ----------------
__global__ void f32_to_bf16_kernel(const float4* __restrict__ in,
                                   __nv_bfloat162* __restrict__ out, int n4) {
    int i = blockIdx.x * blockDim.x + threadIdx.x;
    if (i < n4) {
        float4 v = in[i];
        out[2 * i + 0] = __floats2bfloat162_rn(v.x, v.y);
        out[2 * i + 1] = __floats2bfloat162_rn(v.z, v.w);
    }
}

__global__ void relu_f32_to_bf16_kernel(const float4* __restrict__ in,
                                        __nv_bfloat162* __restrict__ out, int n4) {
    int i = blockIdx.x * blockDim.x + threadIdx.x;
    if (i < n4) {
        float4 v = in[i];
        v.x = fmaxf(v.x, 0.f); v.y = fmaxf(v.y, 0.f);
        v.z = fmaxf(v.z, 0.f); v.w = fmaxf(v.w, 0.f);
        out[2 * i + 0] = __floats2bfloat162_rn(v.x, v.y);
        out[2 * i + 1] = __floats2bfloat162_rn(v.z, v.w);
    }
}

// ---------------- shared mma helpers ----------------
__device__ __forceinline__ void cp_async16(uint32_t smem, const void* g) {
    asm volatile("cp.async.cg.shared.global [%0], [%1], 16;\n" :: "r"(smem), "l"(g));
}
__device__ __forceinline__ void cp_commit() {
    asm volatile("cp.async.commit_group;\n" ::: "memory");
}
__device__ __forceinline__ void ldm4(uint32_t& a, uint32_t& b, uint32_t& c, uint32_t& d,
                                     uint32_t addr) {
    asm volatile("ldmatrix.sync.aligned.m8n8.x4.shared.b16 {%0,%1,%2,%3}, [%4];"
                 : "=r"(a), "=r"(b), "=r"(c), "=r"(d) : "r"(addr));
}
__device__ __forceinline__ void ldm2(uint32_t& a, uint32_t& b, uint32_t addr) {
    asm volatile("ldmatrix.sync.aligned.m8n8.x2.shared.b16 {%0,%1}, [%2];"
                 : "=r"(a), "=r"(b) : "r"(addr));
}
__device__ __forceinline__ void mma_bf16(float* c, const uint32_t* a, const uint32_t* b) {
    asm volatile(
        "mma.sync.aligned.m16n8k16.row.col.f32.bf16.bf16.f32 "
        "{%0,%1,%2,%3}, {%4,%5,%6,%7}, {%8,%9}, {%0,%1,%2,%3};"
        : "+f"(c[0]), "+f"(c[1]), "+f"(c[2]), "+f"(c[3])
        : "r"(a[0]), "r"(a[1]), "r"(a[2]), "r"(a[3]), "r"(b[0]), "r"(b[1]));
}

// smem element offset, row stride 512 bf16 (1024B), 16B-chunk swizzle by row&7
__device__ __forceinline__ int toff(int row, int k) {
    return row * 512 + (((k >> 3) ^ (row & 7)) << 3) + (k & 7);
}

// ---------------- squeeze on mma: enc = relu(hidden) @ W_sq^T + b_sq ----------------
// Grid: (16 j-slabs x 2 m-halves) = 32 CTAs, 256 threads.
// Per CTA: 64 batch rows x 32 j, K = 1024 in two 512-chunks.
#define SQ_SMA (64 * 512 * 2)   // 64KB
#define SQ_SMB (32 * 512 * 2)   // 32KB

__global__ __launch_bounds__(256, 1) void squeeze_mma_kernel(
    const float* __restrict__ bias,
    float* __restrict__ F0, float* __restrict__ F1,
    __nv_bfloat16* __restrict__ Hh0, __nv_bfloat16* __restrict__ Hh1) {
    extern __shared__ __align__(128) char dsm[];
    const uint32_t saA = (uint32_t)__cvta_generic_to_shared(dsm);
    const uint32_t saB = saA + SQ_SMA;

    const int jslab = blockIdx.x & 15;
    const int mhalf = blockIdx.x >> 4;
    const int j0  = jslab * 32;
    const int bm0 = mhalf * 64;
    const int tid = threadIdx.x;
    const int warp = tid >> 5, lane = tid & 31;
    const int wm = warp >> 2, wn = warp & 3;

    float acc[2][4] = {};

    for (int k0 = 0; k0 < HID; k0 += 512) {
        for (int c = tid; c < 4096; c += 256) {
            int row = c >> 6, ch = c & 63;
            cp_async16(saA + (uint32_t)(row * 512 + ((ch ^ (row & 7)) << 3)) * 2,
                       g_enc16 + (size_t)(bm0 + row) * HID + k0 + ch * 8);
        }
        for (int c = tid; c < 2048; c += 256) {
            int row = c >> 6, ch = c & 63;
            cp_async16(saB + (uint32_t)(row * 512 + ((ch ^ (row & 7)) << 3)) * 2,
                       g_wsq16 + (size_t)(j0 + row) * HID + k0 + ch * 8);
        }
        cp_commit();
        asm volatile("cp.async.wait_group 0;\n" ::: "memory");
        __syncthreads();

#pragma unroll 4
        for (int ks = 0; ks < 32; ks++) {
            const int kk0 = ks * 16;
            uint32_t afr[2][4];
#pragma unroll
            for (int mt = 0; mt < 2; mt++) {
                int row = wm * 32 + mt * 16 + (lane & 15);
                int kk = kk0 + ((lane >> 4) << 3);
                ldm4(afr[mt][0], afr[mt][1], afr[mt][2], afr[mt][3],
                     saA + (uint32_t)toff(row, kk) * 2);
            }
            uint32_t bfr[2];
            {
                int row = wn * 8 + (lane & 7);
                int kk = kk0 + (((lane >> 3) & 1) << 3);
                ldm2(bfr[0], bfr[1], saB + (uint32_t)toff(row, kk) * 2);
            }
#pragma unroll
            for (int mt = 0; mt < 2; mt++)
                mma_bf16(acc[mt], afr[mt], bfr);
        }
        __syncthreads();
    }

    const int jbase = j0 + wn * 8 + (lane & 3) * 2;
#pragma unroll
    for (int cc = 0; cc < 2; cc++) {
        const int j = jbase + cc;
        const float bj = bias[j];
#pragma unroll
        for (int mt = 0; mt < 2; mt++) {
            const int bb = bm0 + wm * 32 + mt * 16 + (lane >> 2);
#pragma unroll
            for (int rh = 0; rh < 2; rh++) {
                const int b = bb + rh * 8;
                float v = acc[mt][rh * 2 + cc] + bj;
                __nv_bfloat16 vh = __float2bfloat16(v);
                F0[(size_t)b * H2C + j] = v;
                F1[(size_t)b * H2C + j] = v;
                Hh0[(size_t)b * H2C + j] = vh;
                Hh1[(size_t)b * H2C + j] = vh;
            }
        }
    }
}

// ---------------- persistent GRU: all T steps in one launch ----------------
// Grid: 64 CTAs (16 j-slabs x 2 m-halves x 2 dirs), 256 threads, all co-resident.
// W slab (96KB) loaded into smem ONCE; per step only A (64KB state) is re-loaded.
// Steps separated by a fence-protected global spin barrier.

#define GRU_SMA (64 * 512 * 2)    // 64KB A
#define GRU_SMB (96 * 512 * 2)    // 96KB B
#define GRU_NCTA 64

__device__ __forceinline__ void grid_barrier() {
    __syncthreads();
    if (threadIdx.x == 0) {
        __threadfence();
        unsigned g = *(volatile unsigned*)&g_gen;
        if (atomicAdd(&g_bar, 1u) == GRU_NCTA - 1) {
            *(volatile unsigned*)&g_bar = 0u;
            __threadfence();
            atomicAdd(&g_gen, 1u);
        } else {
            while (*(volatile unsigned*)&g_gen == g) { }
        }
        __threadfence();
    }
    __syncthreads();
}

__global__ __launch_bounds__(256, 1) void gru_persistent_kernel(
    const float* __restrict__ b_ih_f, const float* __restrict__ b_ih_r,
    const float* __restrict__ b_hh_f, const float* __restrict__ b_hh_r,
    int T) {
    extern __shared__ __align__(128) char dsm[];
    const uint32_t saA = (uint32_t)__cvta_generic_to_shared(dsm);
    const uint32_t saB = saA + GRU_SMA;

    const int jslab = blockIdx.x & 15;
    const int mhalf = (blockIdx.x >> 4) & 1;
    const int dir   = blockIdx.x >> 5;
    const int j0  = jslab * 32;
    const int bm0 = mhalf * 64;
    const int tid = threadIdx.x;
    const int warp = tid >> 5, lane = tid & 31;
    const int wm = warp >> 2, wn = warp & 3;

    const __nv_bfloat16* __restrict__ W16 = g_whh16[dir];
    const float* __restrict__ bih = dir ? b_ih_r : b_ih_f;
    const float* __restrict__ bhh = dir ? b_hh_r : b_hh_f;

    // ---- W slab into smem once: 96 rows x 512 k ----
    for (int c = tid; c < 6144; c += 256) {
        int row = c >> 6, ch = c & 63;
        int gate = row >> 5, jl = row & 31;
        cp_async16(saB + (uint32_t)(row * 512 + ((ch ^ (row & 7)) << 3)) * 2,
                   W16 + (size_t)(gate * H2C + j0 + jl) * 512 + ch * 8);
    }
    cp_commit();

    // bias prefetch (registers, loop-invariant)
    const int jbase = j0 + wn * 8 + (lane & 3) * 2;
    float biR[2], biZ[2], biN[2], bhN[2];
#pragma unroll
    for (int cc = 0; cc < 2; cc++) {
        const int j = jbase + cc;
        biR[cc] = bih[j] + bhh[j];
        biZ[cc] = bih[H2C + j] + bhh[H2C + j];
        biN[cc] = bih[2 * H2C + j];
        bhN[cc] = bhh[2 * H2C + j];
    }
    asm volatile("cp.async.wait_group 0;\n" ::: "memory");
    __syncthreads();

    for (int t = 0; t < T; t++) {
        const int pin = t & 1, pout = (t + 1) & 1;
        const __nv_bfloat16* __restrict__ Ah = g_state_h[pin][dir];
        const float* __restrict__ Fin  = g_state_f[pin][dir];
        float* __restrict__ Fout       = g_state_f[pout][dir];
        __nv_bfloat16* __restrict__ Hout = g_state_h[pout][dir];

        // A tile: 64 rows x 512 k
        for (int c = tid; c < 4096; c += 256) {
            int row = c >> 6, ch = c & 63;
            cp_async16(saA + (uint32_t)(row * 512 + ((ch ^ (row & 7)) << 3)) * 2,
                       Ah + (size_t)(bm0 + row) * 512 + ch * 8);
        }
        cp_commit();
        asm volatile("cp.async.wait_group 0;\n" ::: "memory");
        __syncthreads();

        float acc[2][3][4] = {};   // [m-tile][gate][frag]

#pragma unroll 4
        for (int ks = 0; ks < 32; ks++) {
            const int kk0 = ks * 16;
            uint32_t afr[2][4];
#pragma unroll
            for (int mt = 0; mt < 2; mt++) {
                int row = wm * 32 + mt * 16 + (lane & 15);
                int kk = kk0 + ((lane >> 4) << 3);
                ldm4(afr[mt][0], afr[mt][1], afr[mt][2], afr[mt][3],
                     saA + (uint32_t)toff(row, kk) * 2);
            }
            uint32_t bfr[3][2];
#pragma unroll
            for (int g = 0; g < 3; g++) {
                int row = g * 32 + wn * 8 + (lane & 7);
                int kk = kk0 + (((lane >> 3) & 1) << 3);
                ldm2(bfr[g][0], bfr[g][1], saB + (uint32_t)toff(row, kk) * 2);
            }
#pragma unroll
            for (int mt = 0; mt < 2; mt++)
#pragma unroll
                for (int g = 0; g < 3; g++)
                    mma_bf16(acc[mt][g], afr[mt], bfr[g]);
        }

        // epilogue: gates + state update + hcat write
        const int tt = dir ? (T - 1 - t) : t;
#pragma unroll
        for (int cc = 0; cc < 2; cc++) {
            const int j = jbase + cc;
#pragma unroll
            for (int mt = 0; mt < 2; mt++) {
                const int bb = bm0 + wm * 32 + mt * 16 + (lane >> 2);
#pragma unroll
                for (int rh = 0; rh < 2; rh++) {
                    const int b = bb + rh * 8;
                    const int idx = rh * 2 + cc;
                    float r = 1.f / (1.f + __expf(-(biR[cc] + acc[mt][0][idx])));
                    float z = 1.f / (1.f + __expf(-(biZ[cc] + acc[mt][1][idx])));
                    float n = tanhf(biN[cc] + r * (acc[mt][2][idx] + bhN[cc]));
                    float hold = Fin[(size_t)b * H2C + j];
                    float hn = (1.f - z) * n + z * hold;
                    Fout[(size_t)b * H2C + j] = hn;
                    __nv_bfloat16 hb = __float2bfloat16(hn);
                    Hout[(size_t)b * H2C + j] = hb;
                    g_hcat[((size_t)tt * BATCH + b) * HID + dir * H2C + j] = hb;
                }
            }
        }
        __syncthreads();   // A smem reuse safety before next step's cp.async
        grid_barrier();    // publish state to all CTAs
    }
}

// ---------------- big bf16 GEMM: C[M,N] = A[M,K] @ B[N,K]^T + bias ----------------
// BM=128, BN=256, BK=32, 256 threads = 8 warps (2m x 4n), warp tile 64x64,
// mma.sync m16n8k16 bf16, 4-stage cp.async pipeline in dynamic smem.

__device__ __forceinline__ int sw_off(int row, int k) {
    // row stride 32 bf16 (64B); 16B chunks xor-swizzled by (row>>1)&3
    return row * 32 + ((((k >> 3) ^ ((row >> 1) & 3)) & 3) << 3) + (k & 7);
}

#define BG_ABYTES 8192     // 128 rows x 32 k x 2B per stage
#define BG_BBYTES 16384    // 256 rows x 32 k x 2B per stage
#define BG_NSTG   4

__global__ __launch_bounds__(256, 1) void gemm_big_bf16(
    const __nv_bfloat16* __restrict__ Ag, const __nv_bfloat16* __restrict__ Bg,
    const float* __restrict__ bias, float* __restrict__ Cg,
    int M, int N, int K) {
    extern __shared__ __align__(128) char dsm[];
    const uint32_t sa = (uint32_t)__cvta_generic_to_shared(dsm);
    const uint32_t saA = sa;                              // 4 stages x 8KB
    const uint32_t saB = sa + BG_NSTG * BG_ABYTES;        // 4 stages x 16KB

    const int tid = threadIdx.x;
    const int warp = tid >> 5, lane = tid & 31;
    const int wm = warp >> 2, wn = warp & 3;
    const int m0 = blockIdx.x * 128, n0 = blockIdx.y * 256;

    const int r0 = tid >> 2, c0 = tid & 3;
    const uint32_t off0 = (uint32_t)sw_off(r0,       c0 * 8) * 2;
    const uint32_t off1 = (uint32_t)sw_off(r0 + 64,  c0 * 8) * 2;
    const uint32_t off2 = (uint32_t)sw_off(r0 + 128, c0 * 8) * 2;
    const uint32_t off3 = (uint32_t)sw_off(r0 + 192, c0 * 8) * 2;

    const __nv_bfloat16* Arow0 = Ag + (size_t)(m0 + r0) * K + c0 * 8;
    const __nv_bfloat16* Arow1 = Ag + (size_t)(m0 + r0 + 64) * K + c0 * 8;
    const __nv_bfloat16* Brow0 = Bg + (size_t)(n0 + r0) * K + c0 * 8;
    const __nv_bfloat16* Brow1 = Bg + (size_t)(n0 + r0 + 64) * K + c0 * 8;
    const __nv_bfloat16* Brow2 = Bg + (size_t)(n0 + r0 + 128) * K + c0 * 8;
    const __nv_bfloat16* Brow3 = Bg + (size_t)(n0 + r0 + 192) * K + c0 * 8;

    float acc[4][8][4] = {};
    const int NK = K / 32;   // 32

    auto load_stage = [&](int kt) {
        const int s = kt & (BG_NSTG - 1);
        const uint32_t ba = saA + (uint32_t)(s * BG_ABYTES);
        const uint32_t bb = saB + (uint32_t)(s * BG_BBYTES);
        cp_async16(ba + off0, Arow0 + kt * 32);
        cp_async16(ba + off1, Arow1 + kt * 32);
        cp_async16(bb + off0, Brow0 + kt * 32);
        cp_async16(bb + off1, Brow1 + kt * 32);
        cp_async16(bb + off2, Brow2 + kt * 32);
        cp_async16(bb + off3, Brow3 + kt * 32);
        cp_commit();
    };

    load_stage(0);
    load_stage(1);
    load_stage(2);

    for (int kt = 0; kt < NK; kt++) {
        if (kt + 3 < NK) {
            load_stage(kt + 3);
            asm volatile("cp.async.wait_group 3;\n" ::: "memory");
        } else if (kt + 2 < NK) {
            asm volatile("cp.async.wait_group 2;\n" ::: "memory");
        } else if (kt + 1 < NK) {
            asm volatile("cp.async.wait_group 1;\n" ::: "memory");
        } else {
            asm volatile("cp.async.wait_group 0;\n" ::: "memory");
        }
        __syncthreads();

        const int s = kt & (BG_NSTG - 1);
        const uint32_t baseA = saA + (uint32_t)(s * BG_ABYTES);
        const uint32_t baseB = saB + (uint32_t)(s * BG_BBYTES);

#pragma unroll
        for (int ks = 0; ks < 32; ks += 16) {
            uint32_t afr[4][4];
#pragma unroll
            for (int mi = 0; mi < 4; mi++) {
                int row = wm * 64 + mi * 16 + (lane & 15);
                int kk = ks + ((lane >> 4) << 3);
                ldm4(afr[mi][0], afr[mi][1], afr[mi][2], afr[mi][3],
                     baseA + (uint32_t)sw_off(row, kk) * 2);
            }
            uint32_t bfr[8][2];
#pragma unroll
            for (int ni = 0; ni < 4; ni++) {
                int row = wn * 64 + ni * 16 + ((lane >> 4) << 3) + (lane & 7);
                int kk = ks + (((lane >> 3) & 1) << 3);
                uint32_t q0, q1, q2, q3;
                ldm4(q0, q1, q2, q3, baseB + (uint32_t)sw_off(row, kk) * 2);
                bfr[ni * 2 + 0][0] = q0; bfr[ni * 2 + 0][1] = q1;
                bfr[ni * 2 + 1][0] = q2; bfr[ni * 2 + 1][1] = q3;
            }
#pragma unroll
            for (int mi = 0; mi < 4; mi++)
#pragma unroll
                for (int nf = 0; nf < 8; nf++)
                    mma_bf16(acc[mi][nf], afr[mi], bfr[nf]);
        }
        __syncthreads();
    }

#pragma unroll
    for (int mi = 0; mi < 4; mi++) {
#pragma unroll
        for (int nf = 0; nf < 8; nf++) {
            int row = m0 + wm * 64 + mi * 16 + (lane >> 2);
            int col = n0 + wn * 64 + nf * 8 + (lane & 3) * 2;
            float b0 = bias[col], b1 = bias[col + 1];
            float2 v0 = make_float2(acc[mi][nf][0] + b0, acc[mi][nf][1] + b1);
            float2 v1 = make_float2(acc[mi][nf][2] + b0, acc[mi][nf][3] + b1);
            *(float2*)&Cg[(size_t)row * N + col] = v0;
            *(float2*)&Cg[(size_t)(row + 8) * N + col] = v1;
        }
    }
}

// ---------------- in-place log_softmax, online (m,s), no smem row cache ----------------
__global__ __launch_bounds__(256) void logsoftmax_kernel(float* __restrict__ out, int V) {
    __shared__ float redM[8], redS[8];
    float* x = out + (size_t)blockIdx.x * V;
    const int tid = threadIdx.x;

    // pass 1: online max + sumexp
    float m = -INFINITY, s = 0.f;
    for (int i = tid * 4; i < V; i += 1024) {
        float4 v = *(const float4*)(x + i);
        float lm = fmaxf(fmaxf(v.x, v.y), fmaxf(v.z, v.w));
        if (lm > m) { s *= __expf(m - lm); m = lm; }
        s += __expf(v.x - m) + __expf(v.y - m) + __expf(v.z - m) + __expf(v.w - m);
    }
    // warp reduce (m,s)
#pragma unroll
    for (int o = 16; o; o >>= 1) {
        float om = __shfl_xor_sync(0xffffffff, m, o);
        float os = __shfl_xor_sync(0xffffffff, s, o);
        float nm = fmaxf(m, om);
        s = s * __expf(m - nm) + os * __expf(om - nm);
        m = nm;
    }
    if ((tid & 31) == 0) { redM[tid >> 5] = m; redS[tid >> 5] = s; }
    __syncthreads();
    if (tid < 32) {
        float mm = (tid < 8) ? redM[tid] : -INFINITY;
        float ss = (tid < 8) ? redS[tid] : 0.f;
#pragma unroll
        for (int o = 4; o; o >>= 1) {
            float om = __shfl_xor_sync(0xffffffff, mm, o);
            float os = __shfl_xor_sync(0xffffffff, ss, o);
            float nm = fmaxf(mm, om);
            ss = ss * __expf(mm - nm) + os * __expf(om - nm);
            mm = nm;
        }
        if (tid == 0) { redM[0] = mm; redS[0] = ss; }
    }
    __syncthreads();
    const float lse = redM[0] + __logf(redS[0]);

    // pass 2: subtract (reads hit L2)
    for (int i = tid * 4; i < V; i += 1024) {
        float4 v = *(const float4*)(x + i);
        v.x -= lse; v.y -= lse; v.z -= lse; v.w -= lse;
        *(float4*)(x + i) = v;
    }
}

// ---------------- launcher ----------------
extern "C" void kernel_launch(void* const* d_in, const int* in_sizes, int n_in,
                              void* d_out, int out_size) {
    const float* hidden = (const float*)d_in[0];
    const float* W_sq   = (const float*)d_in[1];
    const float* b_sq   = (const float*)d_in[2];
    const float* W_hh_f = (const float*)d_in[3];
    const float* b_ih_f = (const float*)d_in[4];
    const float* b_hh_f = (const float*)d_in[5];
    const float* W_hh_r = (const float*)d_in[6];
    const float* b_ih_r = (const float*)d_in[7];
    const float* b_hh_r = (const float*)d_in[8];
    const float* W_out  = (const float*)d_in[9];
    const float* b_out  = (const float*)d_in[10];
    float* out = (float*)d_out;

    const int h2 = in_sizes[2];              // 512
    const int Hh = 2 * h2;                   // 1024
    const int Bb = in_sizes[0] / Hh;         // 128
    const int V  = in_sizes[10];             // 32000
    const int T  = out_size / (Bb * V);      // 32
    if (T > TMAXX) return;

    float* stf;
    __nv_bfloat16 *sth, *whh16, *hcat, *wout, *enc16, *wsq16;
    cudaGetSymbolAddress((void**)&stf, g_state_f);
    cudaGetSymbolAddress((void**)&sth, g_state_h);
    cudaGetSymbolAddress((void**)&whh16, g_whh16);
    cudaGetSymbolAddress((void**)&hcat, g_hcat);
    cudaGetSymbolAddress((void**)&wout, g_wout);
    cudaGetSymbolAddress((void**)&enc16, g_enc16);
    cudaGetSymbolAddress((void**)&wsq16, g_wsq16);

    // 1. conversions: W_out, W_hh x2, W_sq, relu(hidden) -> bf16
    {
        int n4 = V * Hh / 4;
        f32_to_bf16_kernel<<<(n4 + 255) / 256, 256>>>(
            (const float4*)W_out, (__nv_bfloat162*)wout, n4);
        int g4 = 3 * h2 * h2 / 4;
        f32_to_bf16_kernel<<<(g4 + 255) / 256, 256>>>(
            (const float4*)W_hh_f, (__nv_bfloat162*)whh16, g4);
        f32_to_bf16_kernel<<<(g4 + 255) / 256, 256>>>(
            (const float4*)W_hh_r, (__nv_bfloat162*)(whh16 + 3 * H2C * H2C), g4);
        int s4 = h2 * Hh / 4;
        f32_to_bf16_kernel<<<(s4 + 255) / 256, 256>>>(
            (const float4*)W_sq, (__nv_bfloat162*)wsq16, s4);
        int e4 = Bb * Hh / 4;
        relu_f32_to_bf16_kernel<<<(e4 + 255) / 256, 256>>>(
            (const float4*)hidden, (__nv_bfloat162*)enc16, e4);
    }

    // 2. squeeze (mma) -> parity-0 state (fp32 + bf16, both dirs)
    {
        const int smem = SQ_SMA + SQ_SMB;   // 96KB
        cudaFuncSetAttribute(squeeze_mma_kernel,
                             cudaFuncAttributeMaxDynamicSharedMemorySize, smem);
        squeeze_mma_kernel<<<32, 256, smem>>>(
            b_sq, stf, stf + BATCH * H2C, sth, sth + BATCH * H2C);
    }

    // 3. GRU recurrence: ONE persistent launch, W resident in smem
    {
        const int smem = GRU_SMA + GRU_SMB;   // 160KB
        cudaFuncSetAttribute(gru_persistent_kernel,
                             cudaFuncAttributeMaxDynamicSharedMemorySize, smem);
        gru_persistent_kernel<<<GRU_NCTA, 256, smem>>>(
            b_ih_f, b_ih_r, b_hh_f, b_hh_r, T);
    }

    // 4. logits = hcat @ W_out^T + b_out  (bf16 tensor cores, fp32 accum)
    {
        const int M = T * Bb;   // 4096
        const int smem = BG_NSTG * (BG_ABYTES + BG_BBYTES);   // 98304
        cudaFuncSetAttribute(gemm_big_bf16,
                             cudaFuncAttributeMaxDynamicSharedMemorySize, smem);
        gemm_big_bf16<<<dim3(M / 128, V / 256), 256, smem>>>(
            hcat, wout, b_out, out, M, V, Hh);
    }

    // 5. in-place log_softmax per row
    logsoftmax_kernel<<<T * Bb, 256>>>(out, V);
}